// round 4
// baseline (speedup 1.0000x reference)
#include <cuda_runtime.h>

#define Nn   100000
#define Ne   3200000
#define NNZn 6400000
#define NF   16

// ---- scratch (device globals; no allocation allowed) ----
__device__ float g_z1[Nn * NF];
__device__ float g_z2[Nn * NF];
__device__ float g_zT[Nn * NF];
__device__ float g_z4[Nn * NF];
__device__ float g_pmy[Nn * NF];
__device__ float g_stats[32];   // [0:16) sum, [16:32) sumsq

// Vectorized fp32 reduction atomic (sm_90+): 1 LTS transaction per 16B.
__device__ __forceinline__ void red_v4(float* p, float4 v) {
    asm volatile("red.global.add.v4.f32 [%0], {%1, %2, %3, %4};"
                 :: "l"(p), "f"(v.x), "f"(v.y), "f"(v.z), "f"(v.w)
                 : "memory");
}

// ---- zero all scratch every call (graph replays reuse buffers) ----
__global__ void zero_all_kernel() {
    int tid = blockIdx.x * blockDim.x + threadIdx.x;
    int stride = gridDim.x * blockDim.x;
    const int n4 = Nn * NF / 4;  // 400000 float4 per buffer
    float4 z = make_float4(0.f, 0.f, 0.f, 0.f);
    float4* b1 = (float4*)g_z1;
    float4* b2 = (float4*)g_z2;
    float4* b3 = (float4*)g_zT;
    float4* b4 = (float4*)g_z4;
    float4* b5 = (float4*)g_pmy;
    for (int i = tid; i < n4; i += stride) {
        b1[i] = z; b2[i] = z; b3[i] = z; b4[i] = z; b5[i] = z;
    }
    if (blockIdx.x == 0 && threadIdx.x < 32) g_stats[threadIdx.x] = 0.f;
}

// ---- one hop: zout[d] += zin[s] over all edges ----
__global__ void hop_kernel(const float* __restrict__ zin,
                           float* __restrict__ zout,
                           const int* __restrict__ src,
                           const int* __restrict__ dst) {
    int e = blockIdx.x * blockDim.x + threadIdx.x;
    if (e >= Ne) return;
    int s = src[e];
    int d = dst[e];
    const float4* zi = (const float4*)(zin + (size_t)s * NF);
    float4 a = __ldg(zi + 0);
    float4 b = __ldg(zi + 1);
    float4 c = __ldg(zi + 2);
    float4 w = __ldg(zi + 3);
    float* zo = zout + (size_t)d * NF;
    red_v4(zo + 0, a);
    red_v4(zo + 4, b);
    red_v4(zo + 8, c);
    red_v4(zo + 12, w);
}

// ---- pm_y[r] += vals[i] * feat_b[c] (COO scatter) ----
__global__ void pm_kernel(const float* __restrict__ fb,
                          const float* __restrict__ vals,
                          const int* __restrict__ rows,
                          const int* __restrict__ cols) {
    int i = blockIdx.x * blockDim.x + threadIdx.x;
    if (i >= NNZn) return;
    int c = cols[i];
    int r = rows[i];
    float v = vals[i];
    const float4* x = (const float4*)(fb + (size_t)c * NF);
    float4 a = __ldg(x + 0);
    float4 b = __ldg(x + 1);
    float4 cc = __ldg(x + 2);
    float4 d = __ldg(x + 3);
    a.x *= v; a.y *= v; a.z *= v; a.w *= v;
    b.x *= v; b.y *= v; b.z *= v; b.w *= v;
    cc.x *= v; cc.y *= v; cc.z *= v; cc.w *= v;
    d.x *= v; d.y *= v; d.z *= v; d.w *= v;
    float* o = g_pmy + (size_t)r * NF;
    red_v4(o + 0, a);
    red_v4(o + 4, b);
    red_v4(o + 8, cc);
    red_v4(o + 12, d);
}

// ---- fused projection + relu + BN-stat accumulation ----
__global__ void final_kernel(const float* __restrict__ fa,
                             const float* __restrict__ deg,
                             const float* __restrict__ Wprev,
                             const float* __restrict__ bprev,
                             const float* __restrict__ Wdeg,
                             const float* __restrict__ bdeg,
                             const float* __restrict__ Wrad,
                             const float* __restrict__ brad,
                             const float* __restrict__ Wfuse,
                             const float* __restrict__ bfuse,
                             const float* __restrict__ z1,
                             const float* __restrict__ z2,
                             const float* __restrict__ z4,
                             const float* __restrict__ pmy,
                             float* __restrict__ out) {
    // sW layout: [0:256) Wprev, [256:512) Wdeg, [512:1280) Wrad(3x256), [1280:1536) Wfuse
    __shared__ float sW[1536];
    __shared__ float sB[16];
    __shared__ float sS[32];
    int t = threadIdx.x;
    for (int i = t; i < 256; i += blockDim.x) {
        sW[i] = Wprev[i];
        sW[256 + i] = Wdeg[i];
        sW[1280 + i] = Wfuse[i];
    }
    for (int i = t; i < 768; i += blockDim.x) sW[512 + i] = Wrad[i];
    if (t < 16)
        sB[t] = bprev[t] + bdeg[t] + brad[t] + brad[16 + t] + brad[32 + t] + bfuse[t];
    if (t < 32) sS[t] = 0.f;
    __syncthreads();

    int i = blockIdx.x * blockDim.x + t;
    bool valid = (i < Nn);

    float res[16];
#pragma unroll
    for (int j = 0; j < 16; j++) res[j] = valid ? sB[j] : 0.f;

    if (valid) {
        float in[16];
        const float4* p = (const float4*)(fa + (size_t)i * NF);
        *(float4*)(in + 0)  = p[0];
        *(float4*)(in + 4)  = p[1];
        *(float4*)(in + 8)  = p[2];
        *(float4*)(in + 12) = p[3];
        float dg = deg[i];
        // prev_proj + deg_proj
#pragma unroll
        for (int k = 0; k < 16; k++) {
            float xv = in[k];
            float xd = xv * dg;
#pragma unroll
            for (int j = 0; j < 16; j++)
                res[j] += xv * sW[k * 16 + j] + xd * sW[256 + k * 16 + j];
        }
        // z1 @ Wrad0
        p = (const float4*)(z1 + (size_t)i * NF);
        *(float4*)(in + 0) = p[0]; *(float4*)(in + 4) = p[1];
        *(float4*)(in + 8) = p[2]; *(float4*)(in + 12) = p[3];
#pragma unroll
        for (int k = 0; k < 16; k++) {
            float xv = in[k];
#pragma unroll
            for (int j = 0; j < 16; j++) res[j] += xv * sW[512 + k * 16 + j];
        }
        // z2 @ Wrad1
        p = (const float4*)(z2 + (size_t)i * NF);
        *(float4*)(in + 0) = p[0]; *(float4*)(in + 4) = p[1];
        *(float4*)(in + 8) = p[2]; *(float4*)(in + 12) = p[3];
#pragma unroll
        for (int k = 0; k < 16; k++) {
            float xv = in[k];
#pragma unroll
            for (int j = 0; j < 16; j++) res[j] += xv * sW[768 + k * 16 + j];
        }
        // z4 @ Wrad2
        p = (const float4*)(z4 + (size_t)i * NF);
        *(float4*)(in + 0) = p[0]; *(float4*)(in + 4) = p[1];
        *(float4*)(in + 8) = p[2]; *(float4*)(in + 12) = p[3];
#pragma unroll
        for (int k = 0; k < 16; k++) {
            float xv = in[k];
#pragma unroll
            for (int j = 0; j < 16; j++) res[j] += xv * sW[1024 + k * 16 + j];
        }
        // pm_y @ Wfuse
        p = (const float4*)(pmy + (size_t)i * NF);
        *(float4*)(in + 0) = p[0]; *(float4*)(in + 4) = p[1];
        *(float4*)(in + 8) = p[2]; *(float4*)(in + 12) = p[3];
#pragma unroll
        for (int k = 0; k < 16; k++) {
            float xv = in[k];
#pragma unroll
            for (int j = 0; j < 16; j++) res[j] += xv * sW[1280 + k * 16 + j];
        }
        // relu on second half of columns
#pragma unroll
        for (int j = 8; j < 16; j++) res[j] = fmaxf(res[j], 0.f);
        // store raw result (normalized in-place later)
        float4* o = (float4*)(out + (size_t)i * NF);
        o[0] = make_float4(res[0], res[1], res[2], res[3]);
        o[1] = make_float4(res[4], res[5], res[6], res[7]);
        o[2] = make_float4(res[8], res[9], res[10], res[11]);
        o[3] = make_float4(res[12], res[13], res[14], res[15]);
    }

    // BN stats: warp reduce then block-shared then global. Invalid threads carry 0.
    unsigned lane = t & 31u;
#pragma unroll
    for (int j = 0; j < 16; j++) {
        float s = res[j];
        float q = res[j] * res[j];
#pragma unroll
        for (int o = 16; o > 0; o >>= 1) {
            s += __shfl_xor_sync(0xffffffffu, s, o);
            q += __shfl_xor_sync(0xffffffffu, q, o);
        }
        if (lane == 0) {
            atomicAdd(&sS[j], s);
            atomicAdd(&sS[16 + j], q);
        }
    }
    __syncthreads();
    if (t < 32) atomicAdd(&g_stats[t], sS[t]);
}

// ---- apply batchnorm in place ----
__global__ void bn_kernel(float* __restrict__ out,
                          const float* __restrict__ gamma,
                          const float* __restrict__ beta) {
    __shared__ float sc[16], sh[16];
    if (threadIdx.x < 16) {
        int j = threadIdx.x;
        const float inv = 1.f / (float)Nn;
        float m = g_stats[j] * inv;
        float var = g_stats[16 + j] * inv - m * m;
        float s = rsqrtf(var + 1e-5f) * gamma[j];
        sc[j] = s;
        sh[j] = beta[j] - m * s;
    }
    __syncthreads();
    int tid = blockIdx.x * blockDim.x + threadIdx.x;
    int stride = gridDim.x * blockDim.x;
    const int n4 = Nn * 4;  // float4 count
    float4* o4 = (float4*)out;
    for (int i = tid; i < n4; i += stride) {
        int cb = (i & 3) * 4;
        float4 v = o4[i];
        v.x = v.x * sc[cb + 0] + sh[cb + 0];
        v.y = v.y * sc[cb + 1] + sh[cb + 1];
        v.z = v.z * sc[cb + 2] + sh[cb + 2];
        v.w = v.w * sc[cb + 3] + sh[cb + 3];
        o4[i] = v;
    }
}

extern "C" void kernel_launch(void* const* d_in, const int* in_sizes, int n_in,
                              void* d_out, int out_size) {
    const float* feat_a  = (const float*)d_in[0];
    const float* feat_b  = (const float*)d_in[1];
    const float* deg     = (const float*)d_in[2];
    const float* pm_vals = (const float*)d_in[3];
    const float* W_prev  = (const float*)d_in[4];
    const float* b_prev  = (const float*)d_in[5];
    const float* W_deg   = (const float*)d_in[6];
    const float* b_deg   = (const float*)d_in[7];
    const float* W_rad   = (const float*)d_in[8];
    const float* b_rad   = (const float*)d_in[9];
    const float* W_fuse  = (const float*)d_in[10];
    const float* b_fuse  = (const float*)d_in[11];
    const float* bn_g    = (const float*)d_in[12];
    const float* bn_b    = (const float*)d_in[13];
    const int*   src     = (const int*)d_in[14];
    const int*   dst     = (const int*)d_in[15];
    const int*   pm_rows = (const int*)d_in[16];
    const int*   pm_cols = (const int*)d_in[17];
    // d_in[18] = radius (always 3 for this problem; hop schedule hardcoded)
    float* out = (float*)d_out;

    float *z1, *z2, *zT, *z4, *pmy;
    cudaGetSymbolAddress((void**)&z1, g_z1);
    cudaGetSymbolAddress((void**)&z2, g_z2);
    cudaGetSymbolAddress((void**)&zT, g_zT);
    cudaGetSymbolAddress((void**)&z4, g_z4);
    cudaGetSymbolAddress((void**)&pmy, g_pmy);

    zero_all_kernel<<<2048, 256>>>();

    const int TB = 256;
    // radius=3 hop chain: z1 = A*fa; z2 = A*z1; zT = A*z2; z4 = A*zT
    hop_kernel<<<(Ne + TB - 1) / TB, TB>>>(feat_a, z1, src, dst);
    hop_kernel<<<(Ne + TB - 1) / TB, TB>>>(z1, z2, src, dst);
    hop_kernel<<<(Ne + TB - 1) / TB, TB>>>(z2, zT, src, dst);
    hop_kernel<<<(Ne + TB - 1) / TB, TB>>>(zT, z4, src, dst);

    pm_kernel<<<(NNZn + TB - 1) / TB, TB>>>(feat_b, pm_vals, pm_rows, pm_cols);

    final_kernel<<<(Nn + TB - 1) / TB, TB>>>(
        feat_a, deg, W_prev, b_prev, W_deg, b_deg, W_rad, b_rad,
        W_fuse, b_fuse, z1, z2, z4, pmy, out);

    bn_kernel<<<1024, 256>>>(out, bn_g, bn_b);
}

// round 6
// speedup vs baseline: 1.3013x; 1.3013x over previous
#include <cuda_runtime.h>

#define Nn   100000
#define Ne   3200000
#define NNZn 6400000
#define NF   16
#define SCAN_C 512
#define NBLK ((Nn + SCAN_C - 1) / SCAN_C)   // 196

// ---- scratch (device globals; no allocation allowed) ----
__device__ __align__(16) float g_z1[Nn * NF];
__device__ __align__(16) float g_z2[Nn * NF];
__device__ __align__(16) float g_zT[Nn * NF];
__device__ __align__(16) float g_z4[Nn * NF];
__device__ __align__(16) float g_pmy[Nn * NF];
__device__ float g_stats[32];   // [0:16) sum, [16:32) sumsq

// CSR build scratch
__device__ int  g_cnt_h[Nn];
__device__ int  g_cnt_p[Nn];
__device__ int  g_rp_h[Nn + 1];
__device__ int  g_rp_p[Nn + 1];
__device__ int  g_cur_h[Nn];
__device__ int  g_cur_p[Nn];
__device__ int  g_bsum_h[NBLK];
__device__ int  g_bsum_p[NBLK];
__device__ int  g_csr_src[Ne];
__device__ __align__(8) int2 g_csr_cv[NNZn];   // (col, val-bits)

// ---- zero counters + stats each call (graph replays reuse buffers) ----
__global__ void zero_small_kernel() {
    int tid = blockIdx.x * blockDim.x + threadIdx.x;
    int stride = gridDim.x * blockDim.x;
    for (int i = tid; i < Nn; i += stride) {
        g_cnt_h[i] = 0;
        g_cnt_p[i] = 0;
    }
    if (blockIdx.x == 0 && threadIdx.x < 32) g_stats[threadIdx.x] = 0.f;
}

// ---- histogram ----
__global__ void hist_kernel(const int* __restrict__ idx, int n, int* __restrict__ cnt) {
    int i = blockIdx.x * blockDim.x + threadIdx.x;
    if (i < n) atomicAdd(&cnt[idx[i]], 1);
}

// ---- 2-level exclusive scan over Nn counts ----
__global__ void scan_reduce(const int* __restrict__ cnt, int* __restrict__ bsum) {
    __shared__ int s[SCAN_C];
    int t = threadIdx.x;
    int i = blockIdx.x * SCAN_C + t;
    s[t] = (i < Nn) ? cnt[i] : 0;
    __syncthreads();
    for (int off = SCAN_C / 2; off > 0; off >>= 1) {
        if (t < off) s[t] += s[t + off];
        __syncthreads();
    }
    if (t == 0) bsum[blockIdx.x] = s[0];
}

__global__ void scan_bsums(int* __restrict__ bsum) {   // NBLK <= 256
    __shared__ int s[256];
    int t = threadIdx.x;
    int v = (t < NBLK) ? bsum[t] : 0;
    s[t] = v;
    __syncthreads();
    for (int off = 1; off < 256; off <<= 1) {
        int x = (t >= off) ? s[t - off] : 0;
        __syncthreads();
        s[t] += x;
        __syncthreads();
    }
    if (t < NBLK) bsum[t] = s[t] - v;   // exclusive
}

__global__ void scan_final(const int* __restrict__ cnt, const int* __restrict__ bsum,
                           int* __restrict__ rp, int* __restrict__ cur, int total) {
    __shared__ int s[SCAN_C];
    int t = threadIdx.x;
    int i = blockIdx.x * SCAN_C + t;
    int v = (i < Nn) ? cnt[i] : 0;
    s[t] = v;
    __syncthreads();
    for (int off = 1; off < SCAN_C; off <<= 1) {
        int x = (t >= off) ? s[t - off] : 0;
        __syncthreads();
        s[t] += x;
        __syncthreads();
    }
    if (i < Nn) {
        int e = bsum[blockIdx.x] + s[t] - v;   // exclusive prefix
        rp[i] = e;
        cur[i] = e;
    }
    if (i == 0) rp[Nn] = total;
}

// ---- scatter into CSR slots ----
__global__ void scat_hop(const int* __restrict__ src, const int* __restrict__ dst) {
    int e = blockIdx.x * blockDim.x + threadIdx.x;
    if (e >= Ne) return;
    int d = dst[e];
    int pos = atomicAdd(&g_cur_h[d], 1);
    g_csr_src[pos] = src[e];
}

__global__ void scat_pm(const int* __restrict__ rows, const int* __restrict__ cols,
                        const float* __restrict__ vals) {
    int i = blockIdx.x * blockDim.x + threadIdx.x;
    if (i >= NNZn) return;
    int r = rows[i];
    int pos = atomicAdd(&g_cur_p[r], 1);
    g_csr_cv[pos] = make_int2(cols[i], __float_as_int(vals[i]));
}

// ---- hop as gather: zout[n] = sum over in-edges of zin[src] ----
// 4 threads per node, each owning one float4 column-slab of the 16-float row.
__global__ void hop_gather(const float* __restrict__ zin, float* __restrict__ zout) {
    int idx = blockIdx.x * blockDim.x + threadIdx.x;
    int node = idx >> 2;
    int l = idx & 3;
    if (node >= Nn) return;
    int e = __ldg(&g_rp_h[node]);
    int end = __ldg(&g_rp_h[node + 1]);
    float4 acc = make_float4(0.f, 0.f, 0.f, 0.f);
    for (; e + 3 < end; e += 4) {
        int s0 = __ldg(&g_csr_src[e + 0]);
        int s1 = __ldg(&g_csr_src[e + 1]);
        int s2 = __ldg(&g_csr_src[e + 2]);
        int s3 = __ldg(&g_csr_src[e + 3]);
        float4 v0 = __ldg((const float4*)(zin + (size_t)s0 * NF) + l);
        float4 v1 = __ldg((const float4*)(zin + (size_t)s1 * NF) + l);
        float4 v2 = __ldg((const float4*)(zin + (size_t)s2 * NF) + l);
        float4 v3 = __ldg((const float4*)(zin + (size_t)s3 * NF) + l);
        acc.x += v0.x + v1.x + v2.x + v3.x;
        acc.y += v0.y + v1.y + v2.y + v3.y;
        acc.z += v0.z + v1.z + v2.z + v3.z;
        acc.w += v0.w + v1.w + v2.w + v3.w;
    }
    for (; e < end; e++) {
        int s = __ldg(&g_csr_src[e]);
        float4 v = __ldg((const float4*)(zin + (size_t)s * NF) + l);
        acc.x += v.x; acc.y += v.y; acc.z += v.z; acc.w += v.w;
    }
    ((float4*)(zout + (size_t)node * NF))[l] = acc;
}

// ---- pm_y[n] = sum vals * feat_b[col] over CSR row ----
__global__ void pm_gather(const float* __restrict__ fb) {
    int idx = blockIdx.x * blockDim.x + threadIdx.x;
    int node = idx >> 2;
    int l = idx & 3;
    if (node >= Nn) return;
    int e = __ldg(&g_rp_p[node]);
    int end = __ldg(&g_rp_p[node + 1]);
    float4 acc = make_float4(0.f, 0.f, 0.f, 0.f);
    for (; e + 3 < end; e += 4) {
        int2 cv0 = __ldg(&g_csr_cv[e + 0]);
        int2 cv1 = __ldg(&g_csr_cv[e + 1]);
        int2 cv2 = __ldg(&g_csr_cv[e + 2]);
        int2 cv3 = __ldg(&g_csr_cv[e + 3]);
        float4 v0 = __ldg((const float4*)(fb + (size_t)cv0.x * NF) + l);
        float4 v1 = __ldg((const float4*)(fb + (size_t)cv1.x * NF) + l);
        float4 v2 = __ldg((const float4*)(fb + (size_t)cv2.x * NF) + l);
        float4 v3 = __ldg((const float4*)(fb + (size_t)cv3.x * NF) + l);
        float w0 = __int_as_float(cv0.y), w1 = __int_as_float(cv1.y);
        float w2 = __int_as_float(cv2.y), w3 = __int_as_float(cv3.y);
        acc.x += v0.x * w0 + v1.x * w1 + v2.x * w2 + v3.x * w3;
        acc.y += v0.y * w0 + v1.y * w1 + v2.y * w2 + v3.y * w3;
        acc.z += v0.z * w0 + v1.z * w1 + v2.z * w2 + v3.z * w3;
        acc.w += v0.w * w0 + v1.w * w1 + v2.w * w2 + v3.w * w3;
    }
    for (; e < end; e++) {
        int2 cv = __ldg(&g_csr_cv[e]);
        float4 v = __ldg((const float4*)(fb + (size_t)cv.x * NF) + l);
        float w = __int_as_float(cv.y);
        acc.x += v.x * w; acc.y += v.y * w; acc.z += v.z * w; acc.w += v.w * w;
    }
    ((float4*)(g_pmy + (size_t)node * NF))[l] = acc;
}

// ---- fused projection + relu + BN-stat accumulation ----
__global__ void final_kernel(const float* __restrict__ fa,
                             const float* __restrict__ deg,
                             const float* __restrict__ Wprev,
                             const float* __restrict__ bprev,
                             const float* __restrict__ Wdeg,
                             const float* __restrict__ bdeg,
                             const float* __restrict__ Wrad,
                             const float* __restrict__ brad,
                             const float* __restrict__ Wfuse,
                             const float* __restrict__ bfuse,
                             const float* __restrict__ z1,
                             const float* __restrict__ z2,
                             const float* __restrict__ z4,
                             const float* __restrict__ pmy,
                             float* __restrict__ out) {
    // sW layout: [0:256) Wprev, [256:512) Wdeg, [512:1280) Wrad(3x256), [1280:1536) Wfuse
    __shared__ float sW[1536];
    __shared__ float sB[16];
    __shared__ float sS[32];
    int t = threadIdx.x;
    for (int i = t; i < 256; i += blockDim.x) {
        sW[i] = Wprev[i];
        sW[256 + i] = Wdeg[i];
        sW[1280 + i] = Wfuse[i];
    }
    for (int i = t; i < 768; i += blockDim.x) sW[512 + i] = Wrad[i];
    if (t < 16)
        sB[t] = bprev[t] + bdeg[t] + brad[t] + brad[16 + t] + brad[32 + t] + bfuse[t];
    if (t < 32) sS[t] = 0.f;
    __syncthreads();

    int i = blockIdx.x * blockDim.x + t;
    bool valid = (i < Nn);

    float res[16];
#pragma unroll
    for (int j = 0; j < 16; j++) res[j] = valid ? sB[j] : 0.f;

    if (valid) {
        float in[16];
        const float4* p = (const float4*)(fa + (size_t)i * NF);
        *(float4*)(in + 0)  = p[0];
        *(float4*)(in + 4)  = p[1];
        *(float4*)(in + 8)  = p[2];
        *(float4*)(in + 12) = p[3];
        float dg = deg[i];
#pragma unroll
        for (int k = 0; k < 16; k++) {
            float xv = in[k];
            float xd = xv * dg;
#pragma unroll
            for (int j = 0; j < 16; j++)
                res[j] += xv * sW[k * 16 + j] + xd * sW[256 + k * 16 + j];
        }
        p = (const float4*)(z1 + (size_t)i * NF);
        *(float4*)(in + 0) = p[0]; *(float4*)(in + 4) = p[1];
        *(float4*)(in + 8) = p[2]; *(float4*)(in + 12) = p[3];
#pragma unroll
        for (int k = 0; k < 16; k++) {
            float xv = in[k];
#pragma unroll
            for (int j = 0; j < 16; j++) res[j] += xv * sW[512 + k * 16 + j];
        }
        p = (const float4*)(z2 + (size_t)i * NF);
        *(float4*)(in + 0) = p[0]; *(float4*)(in + 4) = p[1];
        *(float4*)(in + 8) = p[2]; *(float4*)(in + 12) = p[3];
#pragma unroll
        for (int k = 0; k < 16; k++) {
            float xv = in[k];
#pragma unroll
            for (int j = 0; j < 16; j++) res[j] += xv * sW[768 + k * 16 + j];
        }
        p = (const float4*)(z4 + (size_t)i * NF);
        *(float4*)(in + 0) = p[0]; *(float4*)(in + 4) = p[1];
        *(float4*)(in + 8) = p[2]; *(float4*)(in + 12) = p[3];
#pragma unroll
        for (int k = 0; k < 16; k++) {
            float xv = in[k];
#pragma unroll
            for (int j = 0; j < 16; j++) res[j] += xv * sW[1024 + k * 16 + j];
        }
        p = (const float4*)(pmy + (size_t)i * NF);
        *(float4*)(in + 0) = p[0]; *(float4*)(in + 4) = p[1];
        *(float4*)(in + 8) = p[2]; *(float4*)(in + 12) = p[3];
#pragma unroll
        for (int k = 0; k < 16; k++) {
            float xv = in[k];
#pragma unroll
            for (int j = 0; j < 16; j++) res[j] += xv * sW[1280 + k * 16 + j];
        }
#pragma unroll
        for (int j = 8; j < 16; j++) res[j] = fmaxf(res[j], 0.f);
        float4* o = (float4*)(out + (size_t)i * NF);
        o[0] = make_float4(res[0], res[1], res[2], res[3]);
        o[1] = make_float4(res[4], res[5], res[6], res[7]);
        o[2] = make_float4(res[8], res[9], res[10], res[11]);
        o[3] = make_float4(res[12], res[13], res[14], res[15]);
    }

    unsigned lane = t & 31u;
#pragma unroll
    for (int j = 0; j < 16; j++) {
        float s = res[j];
        float q = res[j] * res[j];
#pragma unroll
        for (int o = 16; o > 0; o >>= 1) {
            s += __shfl_xor_sync(0xffffffffu, s, o);
            q += __shfl_xor_sync(0xffffffffu, q, o);
        }
        if (lane == 0) {
            atomicAdd(&sS[j], s);
            atomicAdd(&sS[16 + j], q);
        }
    }
    __syncthreads();
    if (t < 32) atomicAdd(&g_stats[t], sS[t]);
}

// ---- apply batchnorm in place ----
__global__ void bn_kernel(float* __restrict__ out,
                          const float* __restrict__ gamma,
                          const float* __restrict__ beta) {
    __shared__ float sc[16], sh[16];
    if (threadIdx.x < 16) {
        int j = threadIdx.x;
        const float inv = 1.f / (float)Nn;
        float m = g_stats[j] * inv;
        float var = g_stats[16 + j] * inv - m * m;
        float s = rsqrtf(var + 1e-5f) * gamma[j];
        sc[j] = s;
        sh[j] = beta[j] - m * s;
    }
    __syncthreads();
    int tid = blockIdx.x * blockDim.x + threadIdx.x;
    int stride = gridDim.x * blockDim.x;
    const int n4 = Nn * 4;
    float4* o4 = (float4*)out;
    for (int i = tid; i < n4; i += stride) {
        int cb = (i & 3) * 4;
        float4 v = o4[i];
        v.x = v.x * sc[cb + 0] + sh[cb + 0];
        v.y = v.y * sc[cb + 1] + sh[cb + 1];
        v.z = v.z * sc[cb + 2] + sh[cb + 2];
        v.w = v.w * sc[cb + 3] + sh[cb + 3];
        o4[i] = v;
    }
}

extern "C" void kernel_launch(void* const* d_in, const int* in_sizes, int n_in,
                              void* d_out, int out_size) {
    const float* feat_a  = (const float*)d_in[0];
    const float* feat_b  = (const float*)d_in[1];
    const float* deg     = (const float*)d_in[2];
    const float* pm_vals = (const float*)d_in[3];
    const float* W_prev  = (const float*)d_in[4];
    const float* b_prev  = (const float*)d_in[5];
    const float* W_deg   = (const float*)d_in[6];
    const float* b_deg   = (const float*)d_in[7];
    const float* W_rad   = (const float*)d_in[8];
    const float* b_rad   = (const float*)d_in[9];
    const float* W_fuse  = (const float*)d_in[10];
    const float* b_fuse  = (const float*)d_in[11];
    const float* bn_g    = (const float*)d_in[12];
    const float* bn_b    = (const float*)d_in[13];
    const int*   src     = (const int*)d_in[14];
    const int*   dst     = (const int*)d_in[15];
    const int*   pm_rows = (const int*)d_in[16];
    const int*   pm_cols = (const int*)d_in[17];
    float* out = (float*)d_out;

    float *z1, *z2, *zT, *z4, *pmy;
    int *cnt_h, *cnt_p, *rp_h, *rp_p, *cur_h, *cur_p, *bs_h, *bs_p;
    cudaGetSymbolAddress((void**)&z1, g_z1);
    cudaGetSymbolAddress((void**)&z2, g_z2);
    cudaGetSymbolAddress((void**)&zT, g_zT);
    cudaGetSymbolAddress((void**)&z4, g_z4);
    cudaGetSymbolAddress((void**)&pmy, g_pmy);
    cudaGetSymbolAddress((void**)&cnt_h, g_cnt_h);
    cudaGetSymbolAddress((void**)&cnt_p, g_cnt_p);
    cudaGetSymbolAddress((void**)&rp_h, g_rp_h);
    cudaGetSymbolAddress((void**)&rp_p, g_rp_p);
    cudaGetSymbolAddress((void**)&cur_h, g_cur_h);
    cudaGetSymbolAddress((void**)&cur_p, g_cur_p);
    cudaGetSymbolAddress((void**)&bs_h, g_bsum_h);
    cudaGetSymbolAddress((void**)&bs_p, g_bsum_p);

    const int TB = 256;

    // 1. zero counters/stats
    zero_small_kernel<<<256, TB>>>();

    // 2. histograms
    hist_kernel<<<(Ne + TB - 1) / TB, TB>>>(dst, Ne, cnt_h);
    hist_kernel<<<(NNZn + TB - 1) / TB, TB>>>(pm_rows, NNZn, cnt_p);

    // 3. scans -> rowptr + cursors
    scan_reduce<<<NBLK, SCAN_C>>>(cnt_h, bs_h);
    scan_reduce<<<NBLK, SCAN_C>>>(cnt_p, bs_p);
    scan_bsums<<<1, 256>>>(bs_h);
    scan_bsums<<<1, 256>>>(bs_p);
    scan_final<<<NBLK, SCAN_C>>>(cnt_h, bs_h, rp_h, cur_h, Ne);
    scan_final<<<NBLK, SCAN_C>>>(cnt_p, bs_p, rp_p, cur_p, NNZn);

    // 4. scatter into CSR
    scat_hop<<<(Ne + TB - 1) / TB, TB>>>(src, dst);
    scat_pm<<<(NNZn + TB - 1) / TB, TB>>>(pm_rows, pm_cols, pm_vals);

    // 5. hop chain (radius=3): z1 = A*fa; z2 = A*z1; zT = A*z2; z4 = A*zT
    const int GG = (Nn * 4 + TB - 1) / TB;
    hop_gather<<<GG, TB>>>(feat_a, z1);
    hop_gather<<<GG, TB>>>(z1, z2);
    hop_gather<<<GG, TB>>>(z2, zT);
    hop_gather<<<GG, TB>>>(zT, z4);

    // 6. pm gather
    pm_gather<<<GG, TB>>>(feat_b);

    // 7. fused projections + BN
    final_kernel<<<(Nn + TB - 1) / TB, TB>>>(
        feat_a, deg, W_prev, b_prev, W_deg, b_deg, W_rad, b_rad,
        W_fuse, b_fuse, z1, z2, z4, pmy, out);

    bn_kernel<<<1024, TB>>>(out, bn_g, bn_b);
}

// round 8
// speedup vs baseline: 1.4572x; 1.1198x over previous
#include <cuda_runtime.h>

#define Nn   100000
#define Ne   3200000
#define NNZn 6400000
#define NF   16
#define SCAN_C 512
#define NBLK ((Nn + SCAN_C - 1) / SCAN_C)   // 196

// ---- scratch (device globals; no allocation allowed) ----
__device__ __align__(16) float g_z1[Nn * NF];
__device__ __align__(16) float g_z2[Nn * NF];
__device__ __align__(16) float g_zT[Nn * NF];
__device__ __align__(16) float g_z4[Nn * NF];
__device__ __align__(16) float g_pmy[Nn * NF];
__device__ float g_stats[32];   // [0:16) sum, [16:32) sumsq

// CSR build scratch
__device__ int  g_cnt_h[Nn];
__device__ int  g_cnt_p[Nn];
__device__ int  g_rp_h[Nn + 1];
__device__ int  g_rp_p[Nn + 1];
__device__ int  g_cur_h[Nn];
__device__ int  g_cur_p[Nn];
__device__ int  g_bsum_h[NBLK];
__device__ int  g_bsum_p[NBLK];
__device__ int  g_csr_src[Ne];
__device__ __align__(8) int2 g_csr_cv[NNZn];   // (col, val-bits)

// ---- zero counters + stats each call ----
__global__ void zero_small_kernel() {
    int tid = blockIdx.x * blockDim.x + threadIdx.x;
    int stride = gridDim.x * blockDim.x;
    for (int i = tid; i < Nn; i += stride) {
        g_cnt_h[i] = 0;
        g_cnt_p[i] = 0;
    }
    if (blockIdx.x == 0 && threadIdx.x < 32) g_stats[threadIdx.x] = 0.f;
}

// ---- histogram ----
__global__ void hist_kernel(const int* __restrict__ idx, int n, int* __restrict__ cnt) {
    int i = blockIdx.x * blockDim.x + threadIdx.x;
    if (i < n) atomicAdd(&cnt[idx[i]], 1);
}

// ---- 2-level exclusive scan over Nn counts ----
__global__ void scan_reduce(const int* __restrict__ cnt, int* __restrict__ bsum) {
    __shared__ int s[SCAN_C];
    int t = threadIdx.x;
    int i = blockIdx.x * SCAN_C + t;
    s[t] = (i < Nn) ? cnt[i] : 0;
    __syncthreads();
    for (int off = SCAN_C / 2; off > 0; off >>= 1) {
        if (t < off) s[t] += s[t + off];
        __syncthreads();
    }
    if (t == 0) bsum[blockIdx.x] = s[0];
}

__global__ void scan_bsums(int* __restrict__ bsum) {   // NBLK <= 256
    __shared__ int s[256];
    int t = threadIdx.x;
    int v = (t < NBLK) ? bsum[t] : 0;
    s[t] = v;
    __syncthreads();
    for (int off = 1; off < 256; off <<= 1) {
        int x = (t >= off) ? s[t - off] : 0;
        __syncthreads();
        s[t] += x;
        __syncthreads();
    }
    if (t < NBLK) bsum[t] = s[t] - v;   // exclusive
}

__global__ void scan_final(const int* __restrict__ cnt, const int* __restrict__ bsum,
                           int* __restrict__ rp, int* __restrict__ cur, int total) {
    __shared__ int s[SCAN_C];
    int t = threadIdx.x;
    int i = blockIdx.x * SCAN_C + t;
    int v = (i < Nn) ? cnt[i] : 0;
    s[t] = v;
    __syncthreads();
    for (int off = 1; off < SCAN_C; off <<= 1) {
        int x = (t >= off) ? s[t - off] : 0;
        __syncthreads();
        s[t] += x;
        __syncthreads();
    }
    if (i < Nn) {
        int e = bsum[blockIdx.x] + s[t] - v;   // exclusive prefix
        rp[i] = e;
        cur[i] = e;
    }
    if (i == 0) rp[Nn] = total;
}

// ---- scatter into CSR slots ----
__global__ void scat_hop(const int* __restrict__ src, const int* __restrict__ dst) {
    int e = blockIdx.x * blockDim.x + threadIdx.x;
    if (e >= Ne) return;
    int d = dst[e];
    int pos = atomicAdd(&g_cur_h[d], 1);
    g_csr_src[pos] = src[e];
}

__global__ void scat_pm(const int* __restrict__ rows, const int* __restrict__ cols,
                        const float* __restrict__ vals) {
    int i = blockIdx.x * blockDim.x + threadIdx.x;
    if (i >= NNZn) return;
    int r = rows[i];
    int pos = atomicAdd(&g_cur_p[r], 1);
    g_csr_cv[pos] = make_int2(cols[i], __float_as_int(vals[i]));
}

// ---- hop as gather: zout[n] = sum over in-edges of zin[src] ----
// 4 threads per node, each owning one float4 column-slab. Unroll 8 for MLP.
__global__ void hop_gather(const float* __restrict__ zin, float* __restrict__ zout) {
    int idx = blockIdx.x * blockDim.x + threadIdx.x;
    int node = idx >> 2;
    int l = idx & 3;
    if (node >= Nn) return;
    int e = __ldg(&g_rp_h[node]);
    int end = __ldg(&g_rp_h[node + 1]);
    float4 acc = make_float4(0.f, 0.f, 0.f, 0.f);
    for (; e + 7 < end; e += 8) {
        int s0 = __ldg(&g_csr_src[e + 0]);
        int s1 = __ldg(&g_csr_src[e + 1]);
        int s2 = __ldg(&g_csr_src[e + 2]);
        int s3 = __ldg(&g_csr_src[e + 3]);
        int s4 = __ldg(&g_csr_src[e + 4]);
        int s5 = __ldg(&g_csr_src[e + 5]);
        int s6 = __ldg(&g_csr_src[e + 6]);
        int s7 = __ldg(&g_csr_src[e + 7]);
        float4 v0 = __ldg((const float4*)(zin + (size_t)s0 * NF) + l);
        float4 v1 = __ldg((const float4*)(zin + (size_t)s1 * NF) + l);
        float4 v2 = __ldg((const float4*)(zin + (size_t)s2 * NF) + l);
        float4 v3 = __ldg((const float4*)(zin + (size_t)s3 * NF) + l);
        float4 v4 = __ldg((const float4*)(zin + (size_t)s4 * NF) + l);
        float4 v5 = __ldg((const float4*)(zin + (size_t)s5 * NF) + l);
        float4 v6 = __ldg((const float4*)(zin + (size_t)s6 * NF) + l);
        float4 v7 = __ldg((const float4*)(zin + (size_t)s7 * NF) + l);
        acc.x += (v0.x + v1.x) + (v2.x + v3.x) + (v4.x + v5.x) + (v6.x + v7.x);
        acc.y += (v0.y + v1.y) + (v2.y + v3.y) + (v4.y + v5.y) + (v6.y + v7.y);
        acc.z += (v0.z + v1.z) + (v2.z + v3.z) + (v4.z + v5.z) + (v6.z + v7.z);
        acc.w += (v0.w + v1.w) + (v2.w + v3.w) + (v4.w + v5.w) + (v6.w + v7.w);
    }
    for (; e < end; e++) {
        int s = __ldg(&g_csr_src[e]);
        float4 v = __ldg((const float4*)(zin + (size_t)s * NF) + l);
        acc.x += v.x; acc.y += v.y; acc.z += v.z; acc.w += v.w;
    }
    ((float4*)(zout + (size_t)node * NF))[l] = acc;
}

// ---- pm_y[n] = sum vals * feat_b[col] over CSR row (unroll 8) ----
__global__ void pm_gather(const float* __restrict__ fb) {
    int idx = blockIdx.x * blockDim.x + threadIdx.x;
    int node = idx >> 2;
    int l = idx & 3;
    if (node >= Nn) return;
    int e = __ldg(&g_rp_p[node]);
    int end = __ldg(&g_rp_p[node + 1]);
    float4 acc = make_float4(0.f, 0.f, 0.f, 0.f);
    for (; e + 7 < end; e += 8) {
        int2 cv0 = __ldg(&g_csr_cv[e + 0]);
        int2 cv1 = __ldg(&g_csr_cv[e + 1]);
        int2 cv2 = __ldg(&g_csr_cv[e + 2]);
        int2 cv3 = __ldg(&g_csr_cv[e + 3]);
        int2 cv4 = __ldg(&g_csr_cv[e + 4]);
        int2 cv5 = __ldg(&g_csr_cv[e + 5]);
        int2 cv6 = __ldg(&g_csr_cv[e + 6]);
        int2 cv7 = __ldg(&g_csr_cv[e + 7]);
        float4 v0 = __ldg((const float4*)(fb + (size_t)cv0.x * NF) + l);
        float4 v1 = __ldg((const float4*)(fb + (size_t)cv1.x * NF) + l);
        float4 v2 = __ldg((const float4*)(fb + (size_t)cv2.x * NF) + l);
        float4 v3 = __ldg((const float4*)(fb + (size_t)cv3.x * NF) + l);
        float4 v4 = __ldg((const float4*)(fb + (size_t)cv4.x * NF) + l);
        float4 v5 = __ldg((const float4*)(fb + (size_t)cv5.x * NF) + l);
        float4 v6 = __ldg((const float4*)(fb + (size_t)cv6.x * NF) + l);
        float4 v7 = __ldg((const float4*)(fb + (size_t)cv7.x * NF) + l);
        float w0 = __int_as_float(cv0.y), w1 = __int_as_float(cv1.y);
        float w2 = __int_as_float(cv2.y), w3 = __int_as_float(cv3.y);
        float w4 = __int_as_float(cv4.y), w5 = __int_as_float(cv5.y);
        float w6 = __int_as_float(cv6.y), w7 = __int_as_float(cv7.y);
        acc.x += v0.x * w0 + v1.x * w1 + v2.x * w2 + v3.x * w3
               + v4.x * w4 + v5.x * w5 + v6.x * w6 + v7.x * w7;
        acc.y += v0.y * w0 + v1.y * w1 + v2.y * w2 + v3.y * w3
               + v4.y * w4 + v5.y * w5 + v6.y * w6 + v7.y * w7;
        acc.z += v0.z * w0 + v1.z * w1 + v2.z * w2 + v3.z * w3
               + v4.z * w4 + v5.z * w5 + v6.z * w6 + v7.z * w7;
        acc.w += v0.w * w0 + v1.w * w1 + v2.w * w2 + v3.w * w3
               + v4.w * w4 + v5.w * w5 + v6.w * w6 + v7.w * w7;
    }
    for (; e < end; e++) {
        int2 cv = __ldg(&g_csr_cv[e]);
        float4 v = __ldg((const float4*)(fb + (size_t)cv.x * NF) + l);
        float w = __int_as_float(cv.y);
        acc.x += v.x * w; acc.y += v.y * w; acc.z += v.z * w; acc.w += v.w * w;
    }
    ((float4*)(g_pmy + (size_t)node * NF))[l] = acc;
}

// ---- fused projection + relu + BN-stat accumulation ----
__global__ void final_kernel(const float* __restrict__ fa,
                             const float* __restrict__ deg,
                             const float* __restrict__ Wprev,
                             const float* __restrict__ bprev,
                             const float* __restrict__ Wdeg,
                             const float* __restrict__ bdeg,
                             const float* __restrict__ Wrad,
                             const float* __restrict__ brad,
                             const float* __restrict__ Wfuse,
                             const float* __restrict__ bfuse,
                             const float* __restrict__ z1,
                             const float* __restrict__ z2,
                             const float* __restrict__ z4,
                             const float* __restrict__ pmy,
                             float* __restrict__ out) {
    __shared__ float sW[1536];
    __shared__ float sB[16];
    __shared__ float sS[32];
    int t = threadIdx.x;
    for (int i = t; i < 256; i += blockDim.x) {
        sW[i] = Wprev[i];
        sW[256 + i] = Wdeg[i];
        sW[1280 + i] = Wfuse[i];
    }
    for (int i = t; i < 768; i += blockDim.x) sW[512 + i] = Wrad[i];
    if (t < 16)
        sB[t] = bprev[t] + bdeg[t] + brad[t] + brad[16 + t] + brad[32 + t] + bfuse[t];
    if (t < 32) sS[t] = 0.f;
    __syncthreads();

    int i = blockIdx.x * blockDim.x + t;
    bool valid = (i < Nn);

    float res[16];
#pragma unroll
    for (int j = 0; j < 16; j++) res[j] = valid ? sB[j] : 0.f;

    if (valid) {
        float in[16];
        const float4* p = (const float4*)(fa + (size_t)i * NF);
        *(float4*)(in + 0)  = p[0];
        *(float4*)(in + 4)  = p[1];
        *(float4*)(in + 8)  = p[2];
        *(float4*)(in + 12) = p[3];
        float dg = deg[i];
#pragma unroll
        for (int k = 0; k < 16; k++) {
            float xv = in[k];
            float xd = xv * dg;
#pragma unroll
            for (int j = 0; j < 16; j++)
                res[j] += xv * sW[k * 16 + j] + xd * sW[256 + k * 16 + j];
        }
        p = (const float4*)(z1 + (size_t)i * NF);
        *(float4*)(in + 0) = p[0]; *(float4*)(in + 4) = p[1];
        *(float4*)(in + 8) = p[2]; *(float4*)(in + 12) = p[3];
#pragma unroll
        for (int k = 0; k < 16; k++) {
            float xv = in[k];
#pragma unroll
            for (int j = 0; j < 16; j++) res[j] += xv * sW[512 + k * 16 + j];
        }
        p = (const float4*)(z2 + (size_t)i * NF);
        *(float4*)(in + 0) = p[0]; *(float4*)(in + 4) = p[1];
        *(float4*)(in + 8) = p[2]; *(float4*)(in + 12) = p[3];
#pragma unroll
        for (int k = 0; k < 16; k++) {
            float xv = in[k];
#pragma unroll
            for (int j = 0; j < 16; j++) res[j] += xv * sW[768 + k * 16 + j];
        }
        p = (const float4*)(z4 + (size_t)i * NF);
        *(float4*)(in + 0) = p[0]; *(float4*)(in + 4) = p[1];
        *(float4*)(in + 8) = p[2]; *(float4*)(in + 12) = p[3];
#pragma unroll
        for (int k = 0; k < 16; k++) {
            float xv = in[k];
#pragma unroll
            for (int j = 0; j < 16; j++) res[j] += xv * sW[1024 + k * 16 + j];
        }
        p = (const float4*)(pmy + (size_t)i * NF);
        *(float4*)(in + 0) = p[0]; *(float4*)(in + 4) = p[1];
        *(float4*)(in + 8) = p[2]; *(float4*)(in + 12) = p[3];
#pragma unroll
        for (int k = 0; k < 16; k++) {
            float xv = in[k];
#pragma unroll
            for (int j = 0; j < 16; j++) res[j] += xv * sW[1280 + k * 16 + j];
        }
#pragma unroll
        for (int j = 8; j < 16; j++) res[j] = fmaxf(res[j], 0.f);
        float4* o = (float4*)(out + (size_t)i * NF);
        o[0] = make_float4(res[0], res[1], res[2], res[3]);
        o[1] = make_float4(res[4], res[5], res[6], res[7]);
        o[2] = make_float4(res[8], res[9], res[10], res[11]);
        o[3] = make_float4(res[12], res[13], res[14], res[15]);
    }

    unsigned lane = t & 31u;
#pragma unroll
    for (int j = 0; j < 16; j++) {
        float s = res[j];
        float q = res[j] * res[j];
#pragma unroll
        for (int o = 16; o > 0; o >>= 1) {
            s += __shfl_xor_sync(0xffffffffu, s, o);
            q += __shfl_xor_sync(0xffffffffu, q, o);
        }
        if (lane == 0) {
            atomicAdd(&sS[j], s);
            atomicAdd(&sS[16 + j], q);
        }
    }
    __syncthreads();
    if (t < 32) atomicAdd(&g_stats[t], sS[t]);
}

// ---- apply batchnorm in place ----
__global__ void bn_kernel(float* __restrict__ out,
                          const float* __restrict__ gamma,
                          const float* __restrict__ beta) {
    __shared__ float sc[16], sh[16];
    if (threadIdx.x < 16) {
        int j = threadIdx.x;
        const float inv = 1.f / (float)Nn;
        float m = g_stats[j] * inv;
        float var = g_stats[16 + j] * inv - m * m;
        float s = rsqrtf(var + 1e-5f) * gamma[j];
        sc[j] = s;
        sh[j] = beta[j] - m * s;
    }
    __syncthreads();
    int tid = blockIdx.x * blockDim.x + threadIdx.x;
    int stride = gridDim.x * blockDim.x;
    const int n4 = Nn * 4;
    float4* o4 = (float4*)out;
    for (int i = tid; i < n4; i += stride) {
        int cb = (i & 3) * 4;
        float4 v = o4[i];
        v.x = v.x * sc[cb + 0] + sh[cb + 0];
        v.y = v.y * sc[cb + 1] + sh[cb + 1];
        v.z = v.z * sc[cb + 2] + sh[cb + 2];
        v.w = v.w * sc[cb + 3] + sh[cb + 3];
        o4[i] = v;
    }
}

extern "C" void kernel_launch(void* const* d_in, const int* in_sizes, int n_in,
                              void* d_out, int out_size) {
    const float* feat_a  = (const float*)d_in[0];
    const float* feat_b  = (const float*)d_in[1];
    const float* deg     = (const float*)d_in[2];
    const float* pm_vals = (const float*)d_in[3];
    const float* W_prev  = (const float*)d_in[4];
    const float* b_prev  = (const float*)d_in[5];
    const float* W_deg   = (const float*)d_in[6];
    const float* b_deg   = (const float*)d_in[7];
    const float* W_rad   = (const float*)d_in[8];
    const float* b_rad   = (const float*)d_in[9];
    const float* W_fuse  = (const float*)d_in[10];
    const float* b_fuse  = (const float*)d_in[11];
    const float* bn_g    = (const float*)d_in[12];
    const float* bn_b    = (const float*)d_in[13];
    const int*   src     = (const int*)d_in[14];
    const int*   dst     = (const int*)d_in[15];
    const int*   pm_rows = (const int*)d_in[16];
    const int*   pm_cols = (const int*)d_in[17];
    float* out = (float*)d_out;

    float *z1, *z2, *zT, *z4, *pmy;
    int *cnt_h, *cnt_p, *rp_h, *rp_p, *cur_h, *cur_p, *bs_h, *bs_p;
    cudaGetSymbolAddress((void**)&z1, g_z1);
    cudaGetSymbolAddress((void**)&z2, g_z2);
    cudaGetSymbolAddress((void**)&zT, g_zT);
    cudaGetSymbolAddress((void**)&z4, g_z4);
    cudaGetSymbolAddress((void**)&pmy, g_pmy);
    cudaGetSymbolAddress((void**)&cnt_h, g_cnt_h);
    cudaGetSymbolAddress((void**)&cnt_p, g_cnt_p);
    cudaGetSymbolAddress((void**)&rp_h, g_rp_h);
    cudaGetSymbolAddress((void**)&rp_p, g_rp_p);
    cudaGetSymbolAddress((void**)&cur_h, g_cur_h);
    cudaGetSymbolAddress((void**)&cur_p, g_cur_p);
    cudaGetSymbolAddress((void**)&bs_h, g_bsum_h);
    cudaGetSymbolAddress((void**)&bs_p, g_bsum_p);

    // Lazily-created side stream + events for forked capture (host-side infra;
    // device work is identical every call). Fall back to single-stream if
    // creation fails.
    static cudaStream_t s2 = 0;
    static cudaEvent_t ev_fork = 0, ev_join = 0;
    static int infra_ok = -1;
    if (infra_ok < 0) {
        infra_ok = 1;
        if (cudaStreamCreateWithFlags(&s2, cudaStreamNonBlocking) != cudaSuccess) infra_ok = 0;
        if (infra_ok && cudaEventCreateWithFlags(&ev_fork, cudaEventDisableTiming) != cudaSuccess) infra_ok = 0;
        if (infra_ok && cudaEventCreateWithFlags(&ev_join, cudaEventDisableTiming) != cudaSuccess) infra_ok = 0;
    }
    cudaStream_t sp = infra_ok ? s2 : 0;   // pm-path stream

    const int TB = 256;
    const int GG = (Nn * 4 + TB - 1) / TB;

    // 1. zero counters/stats (both paths depend on this)
    zero_small_kernel<<<256, TB>>>();

    if (infra_ok) {
        cudaEventRecord(ev_fork, 0);
        cudaStreamWaitEvent(sp, ev_fork, 0);
    }

    // ---- pm path (stream sp) ----
    hist_kernel<<<(NNZn + TB - 1) / TB, TB, 0, sp>>>(pm_rows, NNZn, cnt_p);
    scan_reduce<<<NBLK, SCAN_C, 0, sp>>>(cnt_p, bs_p);
    scan_bsums<<<1, 256, 0, sp>>>(bs_p);
    scan_final<<<NBLK, SCAN_C, 0, sp>>>(cnt_p, bs_p, rp_p, cur_p, NNZn);
    scat_pm<<<(NNZn + TB - 1) / TB, TB, 0, sp>>>(pm_rows, pm_cols, pm_vals);
    pm_gather<<<GG, TB, 0, sp>>>(feat_b);
    if (infra_ok) cudaEventRecord(ev_join, sp);

    // ---- hop path (default stream) ----
    hist_kernel<<<(Ne + TB - 1) / TB, TB>>>(dst, Ne, cnt_h);
    scan_reduce<<<NBLK, SCAN_C>>>(cnt_h, bs_h);
    scan_bsums<<<1, 256>>>(bs_h);
    scan_final<<<NBLK, SCAN_C>>>(cnt_h, bs_h, rp_h, cur_h, Ne);
    scat_hop<<<(Ne + TB - 1) / TB, TB>>>(src, dst);
    hop_gather<<<GG, TB>>>(feat_a, z1);
    hop_gather<<<GG, TB>>>(z1, z2);
    hop_gather<<<GG, TB>>>(z2, zT);
    hop_gather<<<GG, TB>>>(zT, z4);

    // join pm path before final
    if (infra_ok) cudaStreamWaitEvent(0, ev_join, 0);

    // 7. fused projections + BN
    final_kernel<<<(Nn + TB - 1) / TB, TB>>>(
        feat_a, deg, W_prev, b_prev, W_deg, b_deg, W_rad, b_rad,
        W_fuse, b_fuse, z1, z2, z4, pmy, out);

    bn_kernel<<<1024, TB>>>(out, bn_g, bn_b);
}